// round 16
// baseline (speedup 1.0000x reference)
#include <cuda_runtime.h>
#include <cuda_bf16.h>
#include <math_constants.h>
#include <cstdint>

// Problem constants (z: 32*2048*64 fp32, codebook: 1024*64 fp32)
#define N_VEC   65536
#define E_DIM   64
#define N_CODE  1024
#define ELEMS   (N_VEC * E_DIM)
#define CAP_L   32                  // candidate slots per (row, quarter-list)

#define ROWS_PER_CTA 512            // 256 HMMA rows + 256 FFMA rows
#define NTHREADS     768            // 16 HMMA warps + 8 FFMA warps
#define CHUNK_CODES  256
#define NCHUNKS      (N_CODE / CHUNK_CODES)   // 4
#define PADU         68             // floats per code row in padded layouts

// ---------------------------------------------------------------------------
// Global scratch (module globals; no runtime allocation)
// ---------------------------------------------------------------------------
__device__ float g_cc[N_CODE];
__device__ float g_cb_pad[N_CODE * PADU];     // tf32-valued fp32, padded rows
__device__ int   g_idx[N_VEC];
__device__ int   g_counts[N_CODE];
__device__ float g_sse_part[8192];
__device__ int   g_cnt4[N_VEC * 4];           // per (row, quarter) counts
__device__ int   g_cand[N_VEC * 4 * CAP_L];   // candidate lists

// ---------------------------------------------------------------------------
// helpers
// ---------------------------------------------------------------------------
__device__ __forceinline__ uint32_t to_tf32(float x) {
    uint32_t r;
    asm("cvt.rna.tf32.f32 %0, %1;" : "=r"(r) : "f"(x));
    return r;
}

__device__ __forceinline__ void mma_m16n8k8_tf32(float* c, const uint32_t* a,
                                                 uint32_t b0, uint32_t b1) {
    asm volatile(
        "mma.sync.aligned.m16n8k8.row.col.f32.tf32.tf32.f32 "
        "{%0,%1,%2,%3}, {%4,%5,%6,%7}, {%8,%9}, {%0,%1,%2,%3};"
        : "+f"(c[0]), "+f"(c[1]), "+f"(c[2]), "+f"(c[3])
        : "r"(a[0]), "r"(a[1]), "r"(a[2]), "r"(a[3]), "r"(b0), "r"(b1));
}

// exact fp32 dot — identical chain to the rel_err-0.0 passing rounds
__device__ __forceinline__ float dot64(const float4* __restrict__ a,
                                       const float4* __restrict__ b) {
    float s = 0.0f;
#pragma unroll
    for (int i = 0; i < 16; i++) {
        float4 x = a[i], y = b[i];
        s = fmaf(x.x, y.x, s);
        s = fmaf(x.y, y.y, s);
        s = fmaf(x.z, y.z, s);
        s = fmaf(x.w, y.w, s);
    }
    return s;
}

// ---------------------------------------------------------------------------
// Kernel 1: cc norms + padded tf32 codebook + zero histogram. 4 x 256.
// ---------------------------------------------------------------------------
__global__ void vq_prep(const float* __restrict__ cb) {
    const int j = blockIdx.x * 256 + threadIdx.x;     // 0..1023
    const float4* p = reinterpret_cast<const float4*>(cb + (size_t)j * E_DIM);
    float s = 0.0f;
#pragma unroll
    for (int i = 0; i < 16; i++) {
        float4 v = p[i];
        s = fmaf(v.x, v.x, s);
        s = fmaf(v.y, v.y, s);
        s = fmaf(v.z, v.z, s);
        s = fmaf(v.w, v.w, s);
        g_cb_pad[j * PADU + 4 * i + 0] = __uint_as_float(to_tf32(v.x));
        g_cb_pad[j * PADU + 4 * i + 1] = __uint_as_float(to_tf32(v.y));
        g_cb_pad[j * PADU + 4 * i + 2] = __uint_as_float(to_tf32(v.z));
        g_cb_pad[j * PADU + 4 * i + 3] = __uint_as_float(to_tf32(v.w));
    }
    g_cc[j] = s;
    g_counts[j] = 0;
}

// ---------------------------------------------------------------------------
// Kernel 2: HYBRID screen. 128 CTAs x 768 threads.
//   Warps 0-15 : tf32 m16n8k8 HMMA screen, 16 rows/warp  (rows [0,256) of CTA)
//   Warps 16-23: fp32 FFMA scan, 1 row/thread            (rows [256,512) of CTA)
//   Shared smem chunk: 256 codes, tf32-valued fp32, padded stride 68.
//   Both emit candidates (prefix-min + margin) into per-(row,quarter) lists.
// ---------------------------------------------------------------------------
#define SMEM_SCREEN (CHUNK_CODES * PADU * 4 + CHUNK_CODES * 4)   // 70656 B

__global__ void __launch_bounds__(NTHREADS, 1)
vq_screen(const float* __restrict__ z) {
    extern __shared__ float s_e[];                       // [256 * 68]
    float* s_cc = s_e + CHUNK_CODES * PADU;              // [256]
    const uint32_t* s_eu = reinterpret_cast<const uint32_t*>(s_e);

    const int tid = threadIdx.x;
    const int lane = tid & 31;
    const int wid = tid >> 5;
    const int ctaRow0 = blockIdx.x * ROWS_PER_CTA;

    // ---------------- per-thread setup ----------------
    // HMMA state
    uint32_t af[8][4];
    int r0 = 0, r1 = 0;
    float marg0 = 0.f, marg1 = 0.f;
    float thr0 = CUDART_INF_F, thr1 = CUDART_INF_F;
    int cnt0 = 0, cnt1 = 0;
    int* cand0 = nullptr;
    int* cand1 = nullptr;
    const int q = lane >> 2;
    const int t4 = lane & 3;
    // FFMA state
    float zr[64];
    int frow = 0;
    float fmarg = 0.f, fthr = CUDART_INF_F;
    int fcnt = 0;
    int* fcand = nullptr;

    if (wid < 16) {
        r0 = ctaRow0 + wid * 16 + q;
        r1 = r0 + 8;
        float sz0 = 0.f, sz1 = 0.f;
#pragma unroll
        for (int k = 0; k < 8; k++) {
            float a = z[(size_t)r0 * E_DIM + k * 8 + t4];
            float b = z[(size_t)r1 * E_DIM + k * 8 + t4];
            float c = z[(size_t)r0 * E_DIM + k * 8 + t4 + 4];
            float d = z[(size_t)r1 * E_DIM + k * 8 + t4 + 4];
            sz0 += fabsf(a) + fabsf(c);
            sz1 += fabsf(b) + fabsf(d);
            af[k][0] = to_tf32(a);
            af[k][1] = to_tf32(b);
            af[k][2] = to_tf32(c);
            af[k][3] = to_tf32(d);
        }
        sz0 += __shfl_xor_sync(0xffffffff, sz0, 1);
        sz0 += __shfl_xor_sync(0xffffffff, sz0, 2);
        sz1 += __shfl_xor_sync(0xffffffff, sz1, 1);
        sz1 += __shfl_xor_sync(0xffffffff, sz1, 2);
        marg0 = sz0 * 1.5e-5f + 1.5e-4f;     // validated margin form
        marg1 = sz1 * 1.5e-5f + 1.5e-4f;
        cand0 = g_cand + ((size_t)r0 * 4 + t4) * CAP_L;
        cand1 = g_cand + ((size_t)r1 * 4 + t4) * CAP_L;
    } else {
        frow = ctaRow0 + 256 + (wid - 16) * 32 + lane;
        const float4* zp = reinterpret_cast<const float4*>(z + (size_t)frow * E_DIM);
        float sz = 0.f;
#pragma unroll
        for (int i = 0; i < 16; i++) {
            float4 v = zp[i];
            sz += fabsf(v.x) + fabsf(v.y) + fabsf(v.z) + fabsf(v.w);
            zr[4 * i + 0] = v.x;
            zr[4 * i + 1] = v.y;
            zr[4 * i + 2] = v.z;
            zr[4 * i + 3] = v.w;
        }
        fmarg = sz * 1.5e-5f + 1.5e-4f;
        fcand = g_cand + ((size_t)frow * 4 + 0) * CAP_L;
    }

    // ---------------- chunk loop ----------------
    for (int c = 0; c < NCHUNKS; c++) {
        __syncthreads();
        // stage chunk: 256 codes x 17 float4 = 4352 float4
        {
            const float4* src = reinterpret_cast<const float4*>(
                g_cb_pad + (size_t)c * CHUNK_CODES * PADU);
            float4* dst = reinterpret_cast<float4*>(s_e);
            for (int i = tid; i < CHUNK_CODES * (PADU / 4); i += NTHREADS)
                dst[i] = src[i];
            if (tid < CHUNK_CODES)
                s_cc[tid] = g_cc[c * CHUNK_CODES + tid];
        }
        __syncthreads();

        if (wid < 16) {
            // -------- HMMA screen over 256 codes (32 n-tiles of 8) --------
            for (int nb = 0; nb < 32; nb++) {
                float acc[4] = {0.f, 0.f, 0.f, 0.f};
#pragma unroll
                for (int ks = 0; ks < 8; ks++) {
                    uint32_t b0 = s_eu[(nb * 8 + q) * PADU + ks * 8 + t4];
                    uint32_t b1 = s_eu[(nb * 8 + q) * PADU + ks * 8 + t4 + 4];
                    mma_m16n8k8_tf32(acc, af[ks], b0, b1);
                }
                const int jl = nb * 8 + 2 * t4;
                const float cca = s_cc[jl], ccb = s_cc[jl + 1];
                const int jg = c * CHUNK_CODES + jl;
                float s00 = fmaf(-2.0f, acc[0], cca);
                float s01 = fmaf(-2.0f, acc[1], ccb);
                float s10 = fmaf(-2.0f, acc[2], cca);
                float s11 = fmaf(-2.0f, acc[3], ccb);
                if (s00 <= thr0) { cand0[cnt0 & (CAP_L - 1)] = jg;     cnt0++; thr0 = fminf(thr0, s00 + marg0); }
                if (s01 <= thr0) { cand0[cnt0 & (CAP_L - 1)] = jg + 1; cnt0++; thr0 = fminf(thr0, s01 + marg0); }
                if (s10 <= thr1) { cand1[cnt1 & (CAP_L - 1)] = jg;     cnt1++; thr1 = fminf(thr1, s10 + marg1); }
                if (s11 <= thr1) { cand1[cnt1 & (CAP_L - 1)] = jg + 1; cnt1++; thr1 = fminf(thr1, s11 + marg1); }
            }
        } else {
            // -------- FFMA scan over 256 codes (1 row/thread) --------
            for (int j = 0; j < CHUNK_CODES; j++) {
                const float4* ep = reinterpret_cast<const float4*>(s_e + j * PADU);
                float a0 = 0.f, a1 = 0.f, a2 = 0.f, a3 = 0.f;
#pragma unroll
                for (int i = 0; i < 4; i++) {
                    float4 e0 = ep[4 * i + 0];
                    float4 e1 = ep[4 * i + 1];
                    float4 e2 = ep[4 * i + 2];
                    float4 e3 = ep[4 * i + 3];
                    a0 = fmaf(zr[16 * i + 0],  e0.x, a0);
                    a0 = fmaf(zr[16 * i + 1],  e0.y, a0);
                    a0 = fmaf(zr[16 * i + 2],  e0.z, a0);
                    a0 = fmaf(zr[16 * i + 3],  e0.w, a0);
                    a1 = fmaf(zr[16 * i + 4],  e1.x, a1);
                    a1 = fmaf(zr[16 * i + 5],  e1.y, a1);
                    a1 = fmaf(zr[16 * i + 6],  e1.z, a1);
                    a1 = fmaf(zr[16 * i + 7],  e1.w, a1);
                    a2 = fmaf(zr[16 * i + 8],  e2.x, a2);
                    a2 = fmaf(zr[16 * i + 9],  e2.y, a2);
                    a2 = fmaf(zr[16 * i + 10], e2.z, a2);
                    a2 = fmaf(zr[16 * i + 11], e2.w, a2);
                    a3 = fmaf(zr[16 * i + 12], e3.x, a3);
                    a3 = fmaf(zr[16 * i + 13], e3.y, a3);
                    a3 = fmaf(zr[16 * i + 14], e3.z, a3);
                    a3 = fmaf(zr[16 * i + 15], e3.w, a3);
                }
                float dot = (a0 + a1) + (a2 + a3);
                float s = fmaf(-2.0f, dot, s_cc[j]);
                if (s <= fthr) {
                    fcand[fcnt & (CAP_L - 1)] = c * CHUNK_CODES + j;
                    fcnt++;
                    fthr = fminf(fthr, s + fmarg);
                }
            }
        }
    }

    // ---------------- writeback counts ----------------
    if (wid < 16) {
        g_cnt4[r0 * 4 + t4] = cnt0;
        g_cnt4[r1 * 4 + t4] = cnt1;
    } else {
        g_cnt4[frow * 4 + 0] = fcnt;
        g_cnt4[frow * 4 + 1] = 0;
        g_cnt4[frow * 4 + 2] = 0;
        g_cnt4[frow * 4 + 3] = 0;
    }
}

// ---------------------------------------------------------------------------
// Kernel 3: exact fp32 recheck + fused epilogue. One warp per row.
// ---------------------------------------------------------------------------
__global__ void __launch_bounds__(256)
vq_recheck(const float* __restrict__ z, const float* __restrict__ cb,
           float* __restrict__ out_idxf, float* __restrict__ out_zq) {
    const int lane = threadIdx.x & 31;
    const int w = threadIdx.x >> 5;
    const int row = blockIdx.x * 8 + w;

    float4 zr[16];
    const float4* zp = reinterpret_cast<const float4*>(z + (size_t)row * E_DIM);
#pragma unroll
    for (int i = 0; i < 16; i++) zr[i] = zp[i];

    float zz = 0.0f;
#pragma unroll
    for (int i = 0; i < 16; i++) {
        float4 v = zr[i];
        zz = fmaf(v.x, v.x, zz);
        zz = fmaf(v.y, v.y, zz);
        zz = fmaf(v.z, v.z, zz);
        zz = fmaf(v.w, v.w, zz);
    }

    const int c0 = g_cnt4[row * 4 + 0];
    const int c1 = g_cnt4[row * 4 + 1];
    const int c2 = g_cnt4[row * 4 + 2];
    const int c3 = g_cnt4[row * 4 + 3];
    const bool full = (c0 > CAP_L) | (c1 > CAP_L) | (c2 > CAP_L) | (c3 > CAP_L);
    const int cum1 = c0, cum2 = c0 + c1, cum3 = cum2 + c2;
    const int total = cum3 + c3;
    const int n_eff = full ? N_CODE : total;
    const int* cand = g_cand + (size_t)row * 4 * CAP_L;

    unsigned long long best = 0xffffffffffffffffull;
    for (int i = lane; i < n_eff; i += 32) {
        int j;
        if (full) {
            j = i;
        } else {
            int qq = (i >= cum1) + (i >= cum2) + (i >= cum3);
            int off = (qq > 0 ? (qq > 1 ? (qq > 2 ? cum3 : cum2) : cum1) : 0);
            j = cand[qq * CAP_L + (i - off)];
        }
        const float4* ep = reinterpret_cast<const float4*>(cb + (size_t)j * E_DIM);
        float dot = dot64(zr, ep);
        float d = fmaf(-2.0f, dot, zz + __ldg(&g_cc[j]));
        unsigned long long pk =
            ((unsigned long long)__float_as_uint(d) << 32) | (unsigned)j;
        best = min(best, pk);
    }
#pragma unroll
    for (int off = 16; off > 0; off >>= 1)
        best = min(best, __shfl_xor_sync(0xffffffff, best, off));
    const int bi = (int)(best & 0xffffffffu);

    if (lane == 0) {
        g_idx[row] = bi;
        out_idxf[row] = (float)bi;
        atomicAdd(&g_counts[bi], 1);
    }

    // fused epilogue (out_zq = out+1 is only 4B aligned -> scalar stores)
    const float2 zf = *reinterpret_cast<const float2*>(z + (size_t)row * E_DIM + 2 * lane);
    const float qx = cb[(size_t)bi * E_DIM + 2 * lane];
    const float qy = cb[(size_t)bi * E_DIM + 2 * lane + 1];
    float dx = qx - zf.x;
    float dy = qy - zf.y;
    float* op = out_zq + (size_t)row * E_DIM + 2 * lane;
    op[0] = zf.x + (qx - zf.x);     // mirror reference STE arithmetic
    op[1] = zf.y + (qy - zf.y);

    float sse = fmaf(dx, dx, dy * dy);
#pragma unroll
    for (int off = 16; off > 0; off >>= 1)
        sse += __shfl_xor_sync(0xffffffff, sse, off);

    __shared__ float wsum[8];
    if (lane == 0) wsum[w] = sse;
    __syncthreads();
    if (threadIdx.x == 0) {
        float s = 0.0f;
#pragma unroll
        for (int k = 0; k < 8; k++) s += wsum[k];
        g_sse_part[blockIdx.x] = s;
    }
}

// ---------------------------------------------------------------------------
// Kernel 4: finalize loss + perplexity
// ---------------------------------------------------------------------------
__global__ void vq_finalize(float* __restrict__ out) {
    __shared__ float red[1024];
    int t = threadIdx.x;

    float s = 0.0f;
#pragma unroll
    for (int k = 0; k < 8; k++) s += g_sse_part[t + k * 1024];
    red[t] = s;
    __syncthreads();
#pragma unroll
    for (int st = 512; st > 0; st >>= 1) {
        if (t < st) red[t] += red[t + st];
        __syncthreads();
    }
    float sse = red[0];
    __syncthreads();

    float c = (float)g_counts[t];
    float em = c * (1.0f / (float)N_VEC);
    red[t] = em * logf(em + 1e-10f);
    __syncthreads();
#pragma unroll
    for (int st = 512; st > 0; st >>= 1) {
        if (t < st) red[t] += red[t + st];
        __syncthreads();
    }
    if (t == 0) {
        float mean = sse * (1.0f / (float)ELEMS);
        out[0] = 1.25f * mean;             // (1 + BETA) * mean((z_q - z)^2)
        out[1 + ELEMS] = expf(-red[0]);    // perplexity
    }
}

// ---------------------------------------------------------------------------
// Launch: out layout = [loss(1) | z_q_st(N*64) | perplexity(1) | idx(N)]
// ---------------------------------------------------------------------------
extern "C" void kernel_launch(void* const* d_in, const int* in_sizes, int n_in,
                              void* d_out, int out_size) {
    const float* z  = (const float*)d_in[0];
    const float* cb = (const float*)d_in[1];
    float* out = (float*)d_out;

    float* out_zq   = out + 1;
    float* out_idxf = out + 2 + ELEMS;

    static bool attr_set = false;
    if (!attr_set) {
        cudaFuncSetAttribute(vq_screen, cudaFuncAttributeMaxDynamicSharedMemorySize,
                             SMEM_SCREEN);
        attr_set = true;
    }

    vq_prep<<<4, 256>>>(cb);
    vq_screen<<<N_VEC / ROWS_PER_CTA, NTHREADS, SMEM_SCREEN>>>(z);
    vq_recheck<<<N_VEC / 8, 256>>>(z, cb, out_idxf, out_zq);
    vq_finalize<<<1, 1024>>>(out);
}